// round 14
// baseline (speedup 1.0000x reference)
#include <cuda_runtime.h>
#include <cuda_fp16.h>
#include <math.h>
#include <stdint.h>

// Problem constants
#define B_   16384
#define F_   1024
#define H_   4096
#define O_   1024
#define E_   16
#define CAP_ 2560   // ceil(1.25 * B * 2 / 16)

// ---------------- scratch (device globals; no allocation allowed) ----------
__device__ __half  g_h[(size_t)E_ * CAP_ * H_];     // expert hidden activations (fp16)
__device__ __half  g_featr[(size_t)B_ * F_];        // features in fp16
__device__ __half  g_W1h[(size_t)E_ * F_ * H_];     // W1 in fp16
__device__ __half  g_W2h[(size_t)E_ * H_ * O_];     // W2 in fp16
__device__ int     g_inv[E_ * CAP_];
__device__ float   g_wslot[E_ * CAP_];
__device__ int     g_count[E_];
__device__ int2    g_route_e[B_];
__device__ float2  g_route_w[B_];

// ---------------- helpers ---------------------------------------------------
__device__ __forceinline__ uint32_t smem_u32(const void* p) {
    uint32_t a;
    asm("{ .reg .u64 t; cvta.to.shared.u64 t, %1; cvt.u32.u64 %0, t; }" : "=r"(a) : "l"(p));
    return a;
}
__device__ __forceinline__ void cp_async16(uint32_t dst, const void* src) {
    asm volatile("cp.async.cg.shared.global [%0], [%1], 16;" :: "r"(dst), "l"(src));
}
__device__ __forceinline__ void cp_commit() { asm volatile("cp.async.commit_group;" ::: "memory"); }
template<int N> __device__ __forceinline__ void cp_wait() {
    asm volatile("cp.async.wait_group %0;" :: "n"(N) : "memory");
}
__device__ __forceinline__ void ldsm_x4(uint32_t r[4], uint32_t addr) {
    asm volatile("ldmatrix.sync.aligned.m8n8.x4.shared.b16 {%0,%1,%2,%3}, [%4];"
                 : "=r"(r[0]), "=r"(r[1]), "=r"(r[2]), "=r"(r[3]) : "r"(addr));
}
__device__ __forceinline__ void ldsm_x4_t(uint32_t r[4], uint32_t addr) {
    asm volatile("ldmatrix.sync.aligned.m8n8.x4.trans.shared.b16 {%0,%1,%2,%3}, [%4];"
                 : "=r"(r[0]), "=r"(r[1]), "=r"(r[2]), "=r"(r[3]) : "r"(addr));
}
__device__ __forceinline__ void mma_f16(float c[4], const uint32_t a[4],
                                        uint32_t b0, uint32_t b1) {
    asm volatile(
        "mma.sync.aligned.m16n8k16.row.col.f32.f16.f16.f32 "
        "{%0,%1,%2,%3}, {%4,%5,%6,%7}, {%8,%9}, {%0,%1,%2,%3};"
        : "+f"(c[0]), "+f"(c[1]), "+f"(c[2]), "+f"(c[3])
        : "r"(a[0]), "r"(a[1]), "r"(a[2]), "r"(a[3]), "r"(b0), "r"(b1));
}
__device__ __forceinline__ void red_add_v2(float* addr, float a, float b) {
    asm volatile("red.global.add.v2.f32 [%0], {%1, %2};"
                 :: "l"(addr), "f"(a), "f"(b) : "memory");
}

// ---------------- fused prep: gating (+feat f2h) interleaved with W1 f2h -----
#define PREP_BLOCKS 10240
#define CONV_ITERS  8                        // 8192*256*8 = 16.78M float4 = W1

__global__ __launch_bounds__(256) void prep_kernel(
    const float* __restrict__ features,
    const float* __restrict__ Wg,
    const float* __restrict__ bg,
    const float* __restrict__ ebias,
    const float* __restrict__ W1,
    __half* __restrict__ featr,
    __half* __restrict__ W1h)
{
    const int bid = blockIdx.x;
    const int q = bid / 5;
    const int r = bid - q * 5;
    if (r == 0) {
        // ---- gating + feature fp16 conversion (8 rows per block) ----
        int warp = threadIdx.x >> 5;
        int lane = threadIdx.x & 31;
        int b = q * 8 + warp;

        const float4* f4 = reinterpret_cast<const float4*>(features + (size_t)b * F_);
        __half2* h2 = reinterpret_cast<__half2*>(featr + (size_t)b * F_);
        float acc[E_];
#pragma unroll
        for (int e = 0; e < E_; e++) acc[e] = 0.f;

        for (int k4 = lane; k4 < F_ / 4; k4 += 32) {
            float4 fv = f4[k4];
            h2[2 * k4]     = __floats2half2_rn(fv.x, fv.y);
            h2[2 * k4 + 1] = __floats2half2_rn(fv.z, fv.w);
#pragma unroll
            for (int e = 0; e < E_; e++) {
                float4 wv = reinterpret_cast<const float4*>(Wg + (size_t)e * F_)[k4];
                acc[e] += fv.x * wv.x + fv.y * wv.y + fv.z * wv.z + fv.w * wv.w;
            }
        }
#pragma unroll
        for (int e = 0; e < E_; e++) {
#pragma unroll
            for (int off = 16; off > 0; off >>= 1)
                acc[e] += __shfl_xor_sync(0xFFFFFFFFu, acc[e], off);
        }
        if (lane == 0) {
            float s[E_];
#pragma unroll
            for (int e = 0; e < E_; e++) s[e] = acc[e] + bg[e] + ebias[e];
            int e0 = 0; float s0 = s[0];
#pragma unroll
            for (int e = 1; e < E_; e++) if (s[e] > s0) { s0 = s[e]; e0 = e; }
            int e1 = -1; float s1 = -3.402823e38f;
#pragma unroll
            for (int e = 0; e < E_; e++) if (e != e0 && s[e] > s1) { s1 = s[e]; e1 = e; }
            float z = expf(s1 - s0);
            float w0 = 1.f / (1.f + z);
            float w1 = z / (1.f + z);
            g_route_e[b] = make_int2(e0, e1);
            g_route_w[b] = make_float2(w0, w1);
        }
    } else {
        // ---- W1 fp32 -> fp16 conversion ----
        int c = q * 4 + (r - 1);                       // 0..8191
        size_t base = (size_t)c * (256 * CONV_ITERS) + threadIdx.x;
#pragma unroll
        for (int it = 0; it < CONV_ITERS; it++) {
            size_t j = base + (size_t)it * 256;
            float4 v = reinterpret_cast<const float4*>(W1)[j];
            reinterpret_cast<__half2*>(W1h)[2 * j]     = __floats2half2_rn(v.x, v.y);
            reinterpret_cast<__half2*>(W1h)[2 * j + 1] = __floats2half2_rn(v.z, v.w);
        }
    }
}

// ---------------- parallel capacity scan: one block per expert ---------------
__global__ __launch_bounds__(1024) void scan_kernel()
{
    const int e = blockIdx.x;
    const int tid = threadIdx.x;
    const int lane = tid & 31;
    const int wid = tid >> 5;
    __shared__ int warp_cnt[32];

    int base = 0;
    for (int start = 0; start < B_; start += 1024) {
        int b = start + tid;
        int2 re = g_route_e[b];
        bool asg = (re.x == e) || (re.y == e);
        unsigned mask = __ballot_sync(0xFFFFFFFFu, asg);
        int lane_pos = __popc(mask & ((1u << lane) - 1u));
        if (lane == 0) warp_cnt[wid] = __popc(mask);
        __syncthreads();
        int wbase = 0, tot = 0;
#pragma unroll
        for (int j = 0; j < 32; j++) {
            int c = warp_cnt[j];
            if (j < wid) wbase += c;
            tot += c;
        }
        int pos = base + wbase + lane_pos;
        if (asg && pos < CAP_) {
            float2 rw = g_route_w[b];
            g_inv[e * CAP_ + pos] = b;
            g_wslot[e * CAP_ + pos] = (re.x == e) ? rw.x : rw.y;
        }
        base += tot;
        __syncthreads();
    }
    if (tid == 0) g_count[e] = base < CAP_ ? base : CAP_;
}

// ---------------- fp16 tensor-core grouped GEMM ------------------------------
// CTA tile 128(m) x 256(n), BK=64, 4-stage cp.async pipeline, 256 threads,
// 1 CTA/SM. 8 warps in a 2(m) x 4(n) grid of 64x64 tiles. This cuts the
// per-MAC smem traffic from 0.094 to 0.086 B (B reads amortize over 2x N),
// raising the crossbar ceiling from ~68% to ~74.5% tensor. 1-CTA serialization
// is mitigated by the 4-stage pipeline + fragment double-buffering.
#define APITCH 144                                  // 128B data + 16B pad
#define BPITCH 528                                  // 512B data + 16B pad
#define STAGE_BYTES (128 * APITCH + 64 * BPITCH)    // 18432 + 33792 = 52224
#define NSTAGE 4
#define SMEM_TOTAL (NSTAGE * STAGE_BYTES)           // 208896
#define MX (CAP_ / 128)                             // 20 gemm x-slices

template<int KD, int ND, bool G1>
__global__ __launch_bounds__(256, 1) void moe_gemm(
    const float* __restrict__ bias, float* __restrict__ out,
    const float* __restrict__ Wsrc, __half* __restrict__ Wdst)
{
    if (G1 && blockIdx.x >= MX) {
        // ---- W2 fp32 -> fp16 conversion slice (512 CTAs x 32768 float4) ----
        int c = ((blockIdx.z * (int)gridDim.y + blockIdx.y) * 2 + ((int)blockIdx.x - MX));
        size_t base = (size_t)c * 32768 + threadIdx.x;
#pragma unroll
        for (int it = 0; it < 128; it++) {
            size_t j = base + (size_t)it * 256;
            float4 v = reinterpret_cast<const float4*>(Wsrc)[j];
            reinterpret_cast<__half2*>(Wdst)[2 * j]     = __floats2half2_rn(v.x, v.y);
            reinterpret_cast<__half2*>(Wdst)[2 * j + 1] = __floats2half2_rn(v.z, v.w);
        }
        return;
    }

    const int e = blockIdx.z;
    const int cnt = g_count[e];
    const int m0 = blockIdx.x * 128;
    if (m0 >= cnt) return;
    const int n0 = blockIdx.y * 256;
    constexpr int NK = KD / 64;

    extern __shared__ char smem_raw[];
    const uint32_t sbase = smem_u32(smem_raw);

    const int tid  = threadIdx.x;
    const int lane = tid & 31;
    const int wid  = tid >> 5;
    const int wm   = wid & 1;      // 2 m-warps of 64 rows
    const int wn   = wid >> 1;     // 4 n-warps of 64 cols

    // ---- loader setup ----
    // A tasks: 128 rows x 8 chunks (16B) = 1024 -> 4 per thread
    // B tasks: 64 rows x 32 chunks = 2048 -> 8 per thread
    const __half* pA[4];
    uint32_t dA[4];
#pragma unroll
    for (int i = 0; i < 4; i++) {
        int t = tid + 256 * i;
        int arow = t >> 3, achunk = t & 7;
        if (G1) {
            int m = m0 + arow;
            int r = (m < cnt) ? g_inv[e * CAP_ + m] : 0;
            pA[i] = g_featr + (size_t)r * KD + achunk * 8;
        } else {
            pA[i] = g_h + ((size_t)e * CAP_ + m0 + arow) * KD + achunk * 8;
        }
        dA[i] = arow * APITCH + achunk * 16;
    }
    const __half* W = G1 ? g_W1h : g_W2h;
    const __half* pB[8];
    uint32_t dB[8];
#pragma unroll
    for (int i = 0; i < 8; i++) {
        int t = tid + 256 * i;
        int brow = t >> 5, bchunk = t & 31;
        pB[i] = W + (size_t)e * KD * ND + (size_t)brow * ND + n0 + bchunk * 8;
        dB[i] = 128 * APITCH + brow * BPITCH + bchunk * 16;
    }

    auto load_stage = [&](int ko, int s) {
        uint32_t st = sbase + s * STAGE_BYTES;
#pragma unroll
        for (int i = 0; i < 4; i++)
            cp_async16(st + dA[i], pA[i] + (size_t)ko * 64);
#pragma unroll
        for (int i = 0; i < 8; i++)
            cp_async16(st + dB[i], pB[i] + (size_t)ko * 64 * ND);
        cp_commit();
    };

    load_stage(0, 0); load_stage(1, 1); load_stage(2, 2);

    // ---- precomputed LDSM base offsets (kk-invariant, relative to stage) ----
    const int a_lrow = (lane & 7) + ((lane >> 3) & 1) * 8;   // 0..15
    const int a_kb   = (lane >> 4);                          // 16B chunk in k16
    const int b_k    = (lane & 7) + ((lane >> 3) & 1) * 8;
    const int b_nb   = (lane >> 4) * 8;

    uint32_t aoff[4], boff[4];
#pragma unroll
    for (int im = 0; im < 4; im++)
        aoff[im] = (wm * 64 + im * 16 + a_lrow) * APITCH + a_kb * 16;
#pragma unroll
    for (int j = 0; j < 4; j++)
        boff[j] = 128 * APITCH + b_k * BPITCH + (wn * 64 + j * 16 + b_nb) * 2;

    float acc[4][8][4];
#pragma unroll
    for (int im = 0; im < 4; im++)
#pragma unroll
        for (int jn = 0; jn < 8; jn++)
#pragma unroll
            for (int q = 0; q < 4; q++) acc[im][jn][q] = 0.f;

    // fragment double buffers
    uint32_t afr[2][4][4], bfr[2][4][4];

    auto load_frags = [&](uint32_t st, int kk, int buf) {
#pragma unroll
        for (int im = 0; im < 4; im++)
            ldsm_x4(afr[buf][im], st + aoff[im] + kk * 32);
#pragma unroll
        for (int j = 0; j < 4; j++)
            ldsm_x4_t(bfr[buf][j], st + boff[j] + kk * (16 * BPITCH));
    };

    auto iter_body = [&](int s) {
        const uint32_t st = sbase + s * STAGE_BYTES;
        load_frags(st, 0, 0);
#pragma unroll
        for (int kk = 0; kk < 4; kk++) {
            if (kk < 3) load_frags(st, kk + 1, (kk + 1) & 1);
            const int cb = kk & 1;
#pragma unroll
            for (int im = 0; im < 4; im++)
#pragma unroll
                for (int jn = 0; jn < 8; jn++)
                    mma_f16(acc[im][jn], afr[cb][im],
                            bfr[cb][jn >> 1][(jn & 1) * 2],
                            bfr[cb][jn >> 1][(jn & 1) * 2 + 1]);
        }
    };

    // ---- branch-free hot loop; last three iterations peeled ----
    int s_cur = 0;          // i % 4
    int s_load = 3;         // (i+3) % 4
    for (int i = 0; i < NK - 3; i++) {
        cp_wait<2>();
        __syncthreads();
        // refill target (i+3)%4 == (i-1)%4: consumed last iter; barrier above
        // guarantees all warps are past it.
        load_stage(i + 3, s_load);
        iter_body(s_cur);
        if (++s_cur == NSTAGE) s_cur = 0;
        if (++s_load == NSTAGE) s_load = 0;
    }
    cp_wait<2>();
    __syncthreads();
    iter_body(s_cur);
    if (++s_cur == NSTAGE) s_cur = 0;
    cp_wait<1>();
    __syncthreads();
    iter_body(s_cur);
    if (++s_cur == NSTAGE) s_cur = 0;
    cp_wait<0>();
    __syncthreads();
    iter_body(s_cur);

    // ---- epilogue ----
    const int gID = lane >> 2;
    const int tig = lane & 3;
    float bb0[8], bb1[8];
#pragma unroll
    for (int jn = 0; jn < 8; jn++) {
        int c = n0 + wn * 64 + jn * 8 + tig * 2;
        bb0[jn] = bias[c];
        bb1[jn] = bias[c + 1];
    }
#pragma unroll
    for (int im = 0; im < 4; im++) {
        int r0 = m0 + wm * 64 + im * 16 + gID;
        int r1 = r0 + 8;
        bool v0 = r0 < cnt, v1 = r1 < cnt;
        if (G1) {
            __half* h0 = g_h + ((size_t)e * CAP_ + r0) * ND;
            __half* h1 = g_h + ((size_t)e * CAP_ + r1) * ND;
#pragma unroll
            for (int jn = 0; jn < 8; jn++) {
                int c = n0 + wn * 64 + jn * 8 + tig * 2;
                if (v0) {
                    __half2 h = __floats2half2_rn(fmaxf(acc[im][jn][0] + bb0[jn], 0.f),
                                                  fmaxf(acc[im][jn][1] + bb1[jn], 0.f));
                    *reinterpret_cast<__half2*>(h0 + c) = h;
                }
                if (v1) {
                    __half2 h = __floats2half2_rn(fmaxf(acc[im][jn][2] + bb0[jn], 0.f),
                                                  fmaxf(acc[im][jn][3] + bb1[jn], 0.f));
                    *reinterpret_cast<__half2*>(h1 + c) = h;
                }
            }
        } else {
            int   i0 = v0 ? g_inv[e * CAP_ + r0] : 0;
            int   i1 = v1 ? g_inv[e * CAP_ + r1] : 0;
            float w0 = v0 ? g_wslot[e * CAP_ + r0] : 0.f;
            float w1 = v1 ? g_wslot[e * CAP_ + r1] : 0.f;
#pragma unroll
            for (int jn = 0; jn < 8; jn++) {
                int c = n0 + wn * 64 + jn * 8 + tig * 2;
                if (v0) {
                    red_add_v2(out + (size_t)i0 * ND + c,
                               w0 * (acc[im][jn][0] + bb0[jn]),
                               w0 * (acc[im][jn][1] + bb1[jn]));
                }
                if (v1) {
                    red_add_v2(out + (size_t)i1 * ND + c,
                               w1 * (acc[im][jn][2] + bb0[jn]),
                               w1 * (acc[im][jn][3] + bb1[jn]));
                }
            }
        }
    }
}

// ---------------- launch ------------------------------------------------------
extern "C" void kernel_launch(void* const* d_in, const int* in_sizes, int n_in,
                              void* d_out, int out_size)
{
    const float* features = (const float*)d_in[0];
    const float* Wg       = (const float*)d_in[1];
    const float* bg       = (const float*)d_in[2];
    const float* W1       = (const float*)d_in[3];
    const float* b1       = (const float*)d_in[4];
    const float* W2       = (const float*)d_in[5];
    const float* b2       = (const float*)d_in[6];
    const float* ebias    = (const float*)d_in[7];
    float* out = (float*)d_out;

    cudaFuncSetAttribute(moe_gemm<F_, H_, true>,
                         cudaFuncAttributeMaxDynamicSharedMemorySize, SMEM_TOTAL);
    cudaFuncSetAttribute(moe_gemm<H_, O_, false>,
                         cudaFuncAttributeMaxDynamicSharedMemorySize, SMEM_TOTAL);

    cudaMemsetAsync(out, 0, (size_t)B_ * O_ * sizeof(float), 0);

    __half* d_featr; cudaGetSymbolAddress((void**)&d_featr, g_featr);
    __half* d_W1h;   cudaGetSymbolAddress((void**)&d_W1h, g_W1h);
    __half* d_W2h;   cudaGetSymbolAddress((void**)&d_W2h, g_W2h);

    prep_kernel<<<PREP_BLOCKS, 256>>>(
        features, Wg, bg, ebias, W1, d_featr, d_W1h);
    scan_kernel<<<E_, 1024>>>();

    // GEMM1 grid carries 2 extra x-slices that convert W2 (done before GEMM2).
    moe_gemm<F_, H_, true ><<<dim3(MX + 2, H_ / 256, E_), 256, SMEM_TOTAL>>>(
        b1, nullptr, W2, d_W2h);
    moe_gemm<H_, O_, false><<<dim3(MX, O_ / 256, E_), 256, SMEM_TOTAL>>>(
        b2, out, nullptr, nullptr);
}

// round 15
// speedup vs baseline: 1.0728x; 1.0728x over previous
#include <cuda_runtime.h>
#include <cuda_fp16.h>
#include <math.h>
#include <stdint.h>

// Problem constants
#define B_   16384
#define F_   1024
#define H_   4096
#define O_   1024
#define E_   16
#define CAP_ 2560   // ceil(1.25 * B * 2 / 16)

// ---------------- scratch (device globals; no allocation allowed) ----------
__device__ __half  g_h[(size_t)E_ * CAP_ * H_];     // expert hidden activations (fp16)
__device__ __half  g_featr[(size_t)B_ * F_];        // features in fp16
__device__ __half  g_W1h[(size_t)E_ * F_ * H_];     // W1 in fp16
__device__ __half  g_W2h[(size_t)E_ * H_ * O_];     // W2 in fp16
__device__ int     g_inv[E_ * CAP_];
__device__ float   g_wslot[E_ * CAP_];
__device__ int     g_count[E_];
__device__ int2    g_route_e[B_];
__device__ float2  g_route_w[B_];

// ---------------- helpers ---------------------------------------------------
__device__ __forceinline__ uint32_t smem_u32(const void* p) {
    uint32_t a;
    asm("{ .reg .u64 t; cvta.to.shared.u64 t, %1; cvt.u32.u64 %0, t; }" : "=r"(a) : "l"(p));
    return a;
}
__device__ __forceinline__ void cp_async16(uint32_t dst, const void* src) {
    asm volatile("cp.async.cg.shared.global [%0], [%1], 16;" :: "r"(dst), "l"(src));
}
__device__ __forceinline__ void cp_commit() { asm volatile("cp.async.commit_group;" ::: "memory"); }
template<int N> __device__ __forceinline__ void cp_wait() {
    asm volatile("cp.async.wait_group %0;" :: "n"(N) : "memory");
}
__device__ __forceinline__ void ldsm_x4(uint32_t r[4], uint32_t addr) {
    asm volatile("ldmatrix.sync.aligned.m8n8.x4.shared.b16 {%0,%1,%2,%3}, [%4];"
                 : "=r"(r[0]), "=r"(r[1]), "=r"(r[2]), "=r"(r[3]) : "r"(addr));
}
__device__ __forceinline__ void ldsm_x4_t(uint32_t r[4], uint32_t addr) {
    asm volatile("ldmatrix.sync.aligned.m8n8.x4.trans.shared.b16 {%0,%1,%2,%3}, [%4];"
                 : "=r"(r[0]), "=r"(r[1]), "=r"(r[2]), "=r"(r[3]) : "r"(addr));
}
__device__ __forceinline__ void mma_f16(float c[4], const uint32_t a[4],
                                        uint32_t b0, uint32_t b1) {
    asm volatile(
        "mma.sync.aligned.m16n8k16.row.col.f32.f16.f16.f32 "
        "{%0,%1,%2,%3}, {%4,%5,%6,%7}, {%8,%9}, {%0,%1,%2,%3};"
        : "+f"(c[0]), "+f"(c[1]), "+f"(c[2]), "+f"(c[3])
        : "r"(a[0]), "r"(a[1]), "r"(a[2]), "r"(a[3]), "r"(b0), "r"(b1));
}
__device__ __forceinline__ void red_add_v2(float* addr, float a, float b) {
    asm volatile("red.global.add.v2.f32 [%0], {%1, %2};"
                 :: "l"(addr), "f"(a), "f"(b) : "memory");
}

// ---------------- fused prep: gating (+feat f2h) interleaved with W1 f2h -----
#define PREP_BLOCKS 10240
#define CONV_ITERS  8                        // 8192*256*8 = 16.78M float4 = W1

__global__ __launch_bounds__(256) void prep_kernel(
    const float* __restrict__ features,
    const float* __restrict__ Wg,
    const float* __restrict__ bg,
    const float* __restrict__ ebias,
    const float* __restrict__ W1,
    __half* __restrict__ featr,
    __half* __restrict__ W1h)
{
    const int bid = blockIdx.x;
    const int q = bid / 5;
    const int r = bid - q * 5;
    if (r == 0) {
        // ---- gating + feature fp16 conversion (8 rows per block) ----
        int warp = threadIdx.x >> 5;
        int lane = threadIdx.x & 31;
        int b = q * 8 + warp;

        const float4* f4 = reinterpret_cast<const float4*>(features + (size_t)b * F_);
        __half2* h2 = reinterpret_cast<__half2*>(featr + (size_t)b * F_);
        float acc[E_];
#pragma unroll
        for (int e = 0; e < E_; e++) acc[e] = 0.f;

        for (int k4 = lane; k4 < F_ / 4; k4 += 32) {
            float4 fv = f4[k4];
            h2[2 * k4]     = __floats2half2_rn(fv.x, fv.y);
            h2[2 * k4 + 1] = __floats2half2_rn(fv.z, fv.w);
#pragma unroll
            for (int e = 0; e < E_; e++) {
                float4 wv = reinterpret_cast<const float4*>(Wg + (size_t)e * F_)[k4];
                acc[e] += fv.x * wv.x + fv.y * wv.y + fv.z * wv.z + fv.w * wv.w;
            }
        }
#pragma unroll
        for (int e = 0; e < E_; e++) {
#pragma unroll
            for (int off = 16; off > 0; off >>= 1)
                acc[e] += __shfl_xor_sync(0xFFFFFFFFu, acc[e], off);
        }
        if (lane == 0) {
            float s[E_];
#pragma unroll
            for (int e = 0; e < E_; e++) s[e] = acc[e] + bg[e] + ebias[e];
            int e0 = 0; float s0 = s[0];
#pragma unroll
            for (int e = 1; e < E_; e++) if (s[e] > s0) { s0 = s[e]; e0 = e; }
            int e1 = -1; float s1 = -3.402823e38f;
#pragma unroll
            for (int e = 0; e < E_; e++) if (e != e0 && s[e] > s1) { s1 = s[e]; e1 = e; }
            float z = expf(s1 - s0);
            float w0 = 1.f / (1.f + z);
            float w1 = z / (1.f + z);
            g_route_e[b] = make_int2(e0, e1);
            g_route_w[b] = make_float2(w0, w1);
        }
    } else {
        // ---- W1 fp32 -> fp16 conversion ----
        int c = q * 4 + (r - 1);                       // 0..8191
        size_t base = (size_t)c * (256 * CONV_ITERS) + threadIdx.x;
#pragma unroll
        for (int it = 0; it < CONV_ITERS; it++) {
            size_t j = base + (size_t)it * 256;
            float4 v = reinterpret_cast<const float4*>(W1)[j];
            reinterpret_cast<__half2*>(W1h)[2 * j]     = __floats2half2_rn(v.x, v.y);
            reinterpret_cast<__half2*>(W1h)[2 * j + 1] = __floats2half2_rn(v.z, v.w);
        }
    }
}

// ---------------- parallel capacity scan: one block per expert ---------------
__global__ __launch_bounds__(1024) void scan_kernel()
{
    const int e = blockIdx.x;
    const int tid = threadIdx.x;
    const int lane = tid & 31;
    const int wid = tid >> 5;
    __shared__ int warp_cnt[32];

    int base = 0;
    for (int start = 0; start < B_; start += 1024) {
        int b = start + tid;
        int2 re = g_route_e[b];
        bool asg = (re.x == e) || (re.y == e);
        unsigned mask = __ballot_sync(0xFFFFFFFFu, asg);
        int lane_pos = __popc(mask & ((1u << lane) - 1u));
        if (lane == 0) warp_cnt[wid] = __popc(mask);
        __syncthreads();
        int wbase = 0, tot = 0;
#pragma unroll
        for (int j = 0; j < 32; j++) {
            int c = warp_cnt[j];
            if (j < wid) wbase += c;
            tot += c;
        }
        int pos = base + wbase + lane_pos;
        if (asg && pos < CAP_) {
            float2 rw = g_route_w[b];
            g_inv[e * CAP_ + pos] = b;
            g_wslot[e * CAP_ + pos] = (re.x == e) ? rw.x : rw.y;
        }
        base += tot;
        __syncthreads();
    }
    if (tid == 0) g_count[e] = base < CAP_ ? base : CAP_;
}

// ---------------- fp16 tensor-core grouped GEMM ------------------------------
// CTA tile 128(m) x 128(n), BK=64, 3-stage cp.async pipeline, 128 threads,
// 2 CTAs/SM, warp tile 64x64, fragment double-buffering, peeled tail.
// VALIDATED OPTIMUM (r13/r14): 2 CTAs/SM is worth ~10 pts of tensor (vs the
// 128x256 1-CTA variant, which regressed despite a higher crossbar ceiling).
// Per-SM crossbar ceiling here is ~68% tensor; measured 65%. Do not retune.
#define APITCH 144                                  // 128B data + 16B pad
#define BPITCH 272                                  // 256B data + 16B pad
#define STAGE_BYTES (128 * APITCH + 64 * BPITCH)    // 35840
#define NSTAGE 3
#define SMEM_TOTAL (NSTAGE * STAGE_BYTES)           // 107520 (x2 CTA = 215040)
#define MX (CAP_ / 128)                             // 20 gemm x-slices

template<int KD, int ND, bool G1>
__global__ __launch_bounds__(128, 2) void moe_gemm(
    const float* __restrict__ bias, float* __restrict__ out,
    const float* __restrict__ Wsrc, __half* __restrict__ Wdst)
{
    if (G1 && blockIdx.x >= MX) {
        // ---- W2 fp32 -> fp16 conversion slice (1024 CTAs x 16384 float4) ----
        int c = ((blockIdx.z * (int)gridDim.y + blockIdx.y) * 2 + ((int)blockIdx.x - MX));
        size_t base = (size_t)c * 16384 + threadIdx.x;
#pragma unroll
        for (int it = 0; it < 128; it++) {
            size_t j = base + (size_t)it * 128;
            float4 v = reinterpret_cast<const float4*>(Wsrc)[j];
            reinterpret_cast<__half2*>(Wdst)[2 * j]     = __floats2half2_rn(v.x, v.y);
            reinterpret_cast<__half2*>(Wdst)[2 * j + 1] = __floats2half2_rn(v.z, v.w);
        }
        return;
    }

    const int e = blockIdx.z;
    const int cnt = g_count[e];
    const int m0 = blockIdx.x * 128;
    if (m0 >= cnt) return;
    const int n0 = blockIdx.y * 128;
    constexpr int NK = KD / 64;

    extern __shared__ char smem_raw[];
    const uint32_t sbase = smem_u32(smem_raw);

    const int tid  = threadIdx.x;
    const int lane = tid & 31;
    const int wid  = tid >> 5;
    const int wm   = wid & 1;      // 2 m-warps of 64 rows
    const int wn   = wid >> 1;     // 2 n-warps of 64 cols

    // ---- loader setup ----
    const __half* pA[8];
    uint32_t dA[8];
#pragma unroll
    for (int i = 0; i < 8; i++) {
        int t = tid + 128 * i;
        int arow = t >> 3, achunk = t & 7;
        if (G1) {
            int m = m0 + arow;
            int r = (m < cnt) ? g_inv[e * CAP_ + m] : 0;
            pA[i] = g_featr + (size_t)r * KD + achunk * 8;
        } else {
            pA[i] = g_h + ((size_t)e * CAP_ + m0 + arow) * KD + achunk * 8;
        }
        dA[i] = arow * APITCH + achunk * 16;
    }
    const __half* W = G1 ? g_W1h : g_W2h;
    const __half* pB[8];
    uint32_t dB[8];
#pragma unroll
    for (int i = 0; i < 8; i++) {
        int t = tid + 128 * i;
        int brow = t >> 4, bchunk = t & 15;
        pB[i] = W + (size_t)e * KD * ND + (size_t)brow * ND + n0 + bchunk * 8;
        dB[i] = 128 * APITCH + brow * BPITCH + bchunk * 16;
    }

    auto load_stage = [&](int ko, int s) {
        uint32_t st = sbase + s * STAGE_BYTES;
#pragma unroll
        for (int i = 0; i < 8; i++)
            cp_async16(st + dA[i], pA[i] + (size_t)ko * 64);
#pragma unroll
        for (int i = 0; i < 8; i++)
            cp_async16(st + dB[i], pB[i] + (size_t)ko * 64 * ND);
        cp_commit();
    };

    load_stage(0, 0); load_stage(1, 1);

    // ---- precomputed LDSM base offsets (kk-invariant, relative to stage) ----
    const int a_lrow = (lane & 7) + ((lane >> 3) & 1) * 8;   // 0..15
    const int a_kb   = (lane >> 4);                          // 16B chunk in k16
    const int b_k    = (lane & 7) + ((lane >> 3) & 1) * 8;
    const int b_nb   = (lane >> 4) * 8;

    uint32_t aoff[4], boff[4];
#pragma unroll
    for (int im = 0; im < 4; im++)
        aoff[im] = (wm * 64 + im * 16 + a_lrow) * APITCH + a_kb * 16;
#pragma unroll
    for (int j = 0; j < 4; j++)
        boff[j] = 128 * APITCH + b_k * BPITCH + (wn * 64 + j * 16 + b_nb) * 2;

    float acc[4][8][4];
#pragma unroll
    for (int im = 0; im < 4; im++)
#pragma unroll
        for (int jn = 0; jn < 8; jn++)
#pragma unroll
            for (int q = 0; q < 4; q++) acc[im][jn][q] = 0.f;

    // fragment double buffers
    uint32_t afr[2][4][4], bfr[2][4][4];

    auto load_frags = [&](uint32_t st, int kk, int buf) {
#pragma unroll
        for (int im = 0; im < 4; im++)
            ldsm_x4(afr[buf][im], st + aoff[im] + kk * 32);
#pragma unroll
        for (int j = 0; j < 4; j++)
            ldsm_x4_t(bfr[buf][j], st + boff[j] + kk * (16 * BPITCH));
    };

    auto iter_body = [&](int s) {
        const uint32_t st = sbase + s * STAGE_BYTES;
        load_frags(st, 0, 0);
#pragma unroll
        for (int kk = 0; kk < 4; kk++) {
            if (kk < 3) load_frags(st, kk + 1, (kk + 1) & 1);
            const int cb = kk & 1;
#pragma unroll
            for (int im = 0; im < 4; im++)
#pragma unroll
                for (int jn = 0; jn < 8; jn++)
                    mma_f16(acc[im][jn], afr[cb][im],
                            bfr[cb][jn >> 1][(jn & 1) * 2],
                            bfr[cb][jn >> 1][(jn & 1) * 2 + 1]);
        }
    };

    // ---- branch-free hot loop; last two iterations peeled ----
    int s_cur = 0;          // i % 3
    int s_load = 2;         // (i+2) % 3
    for (int i = 0; i < NK - 2; i++) {
        cp_wait<1>();
        __syncthreads();
        // refill target (i+2)%3 == (i-1)%3: consumed last iter; barrier above
        // guarantees all warps are past it.
        load_stage(i + 2, s_load);
        iter_body(s_cur);
        if (++s_cur == NSTAGE) s_cur = 0;
        if (++s_load == NSTAGE) s_load = 0;
    }
    cp_wait<1>();
    __syncthreads();
    iter_body(s_cur);
    if (++s_cur == NSTAGE) s_cur = 0;

    // ---- prefetch epilogue metadata before the last mainloop iteration -----
    const int gID = lane >> 2;
    const int tig = lane & 3;
    float bb0[8], bb1[8];
#pragma unroll
    for (int jn = 0; jn < 8; jn++) {
        int c = n0 + wn * 64 + jn * 8 + tig * 2;
        bb0[jn] = bias[c];
        bb1[jn] = bias[c + 1];
    }
    int   rowi[8];
    float roww[8];
    bool  rowv[8];
    if (!G1) {
#pragma unroll
        for (int im = 0; im < 4; im++) {
            int r0 = m0 + wm * 64 + im * 16 + gID;
            int r1 = r0 + 8;
            rowv[2 * im]     = r0 < cnt;
            rowv[2 * im + 1] = r1 < cnt;
            rowi[2 * im]     = rowv[2 * im]     ? g_inv[e * CAP_ + r0] : 0;
            rowi[2 * im + 1] = rowv[2 * im + 1] ? g_inv[e * CAP_ + r1] : 0;
            roww[2 * im]     = rowv[2 * im]     ? g_wslot[e * CAP_ + r0] : 0.f;
            roww[2 * im + 1] = rowv[2 * im + 1] ? g_wslot[e * CAP_ + r1] : 0.f;
        }
    }

    cp_wait<0>();
    __syncthreads();
    iter_body(s_cur);

    // ---- epilogue ----
#pragma unroll
    for (int im = 0; im < 4; im++) {
        int r0 = m0 + wm * 64 + im * 16 + gID;
        int r1 = r0 + 8;
        if (G1) {
            bool v0 = r0 < cnt, v1 = r1 < cnt;
            __half* h0 = g_h + ((size_t)e * CAP_ + r0) * ND;
            __half* h1 = g_h + ((size_t)e * CAP_ + r1) * ND;
#pragma unroll
            for (int jn = 0; jn < 8; jn++) {
                int c = n0 + wn * 64 + jn * 8 + tig * 2;
                if (v0) {
                    __half2 h = __floats2half2_rn(fmaxf(acc[im][jn][0] + bb0[jn], 0.f),
                                                  fmaxf(acc[im][jn][1] + bb1[jn], 0.f));
                    *reinterpret_cast<__half2*>(h0 + c) = h;
                }
                if (v1) {
                    __half2 h = __floats2half2_rn(fmaxf(acc[im][jn][2] + bb0[jn], 0.f),
                                                  fmaxf(acc[im][jn][3] + bb1[jn], 0.f));
                    *reinterpret_cast<__half2*>(h1 + c) = h;
                }
            }
        } else {
            bool  v0 = rowv[2 * im],     v1 = rowv[2 * im + 1];
            int   i0 = rowi[2 * im],     i1 = rowi[2 * im + 1];
            float w0 = roww[2 * im],     w1 = roww[2 * im + 1];
#pragma unroll
            for (int jn = 0; jn < 8; jn++) {
                int c = n0 + wn * 64 + jn * 8 + tig * 2;
                if (v0) {
                    red_add_v2(out + (size_t)i0 * ND + c,
                               w0 * (acc[im][jn][0] + bb0[jn]),
                               w0 * (acc[im][jn][1] + bb1[jn]));
                }
                if (v1) {
                    red_add_v2(out + (size_t)i1 * ND + c,
                               w1 * (acc[im][jn][2] + bb0[jn]),
                               w1 * (acc[im][jn][3] + bb1[jn]));
                }
            }
        }
    }
}

// ---------------- launch ------------------------------------------------------
extern "C" void kernel_launch(void* const* d_in, const int* in_sizes, int n_in,
                              void* d_out, int out_size)
{
    const float* features = (const float*)d_in[0];
    const float* Wg       = (const float*)d_in[1];
    const float* bg       = (const float*)d_in[2];
    const float* W1       = (const float*)d_in[3];
    const float* b1       = (const float*)d_in[4];
    const float* W2       = (const float*)d_in[5];
    const float* b2       = (const float*)d_in[6];
    const float* ebias    = (const float*)d_in[7];
    float* out = (float*)d_out;

    cudaFuncSetAttribute(moe_gemm<F_, H_, true>,
                         cudaFuncAttributeMaxDynamicSharedMemorySize, SMEM_TOTAL);
    cudaFuncSetAttribute(moe_gemm<H_, O_, false>,
                         cudaFuncAttributeMaxDynamicSharedMemorySize, SMEM_TOTAL);

    cudaMemsetAsync(out, 0, (size_t)B_ * O_ * sizeof(float), 0);

    __half* d_featr; cudaGetSymbolAddress((void**)&d_featr, g_featr);
    __half* d_W1h;   cudaGetSymbolAddress((void**)&d_W1h, g_W1h);
    __half* d_W2h;   cudaGetSymbolAddress((void**)&d_W2h, g_W2h);

    prep_kernel<<<PREP_BLOCKS, 256>>>(
        features, Wg, bg, ebias, W1, d_featr, d_W1h);
    scan_kernel<<<E_, 1024>>>();

    // GEMM1 grid carries 2 extra x-slices that convert W2 (done before GEMM2).
    moe_gemm<F_, H_, true ><<<dim3(MX + 2, H_ / 128, E_), 128, SMEM_TOTAL>>>(
        b1, nullptr, W2, d_W2h);
    moe_gemm<H_, O_, false><<<dim3(MX, O_ / 128, E_), 128, SMEM_TOTAL>>>(
        b2, out, nullptr, nullptr);
}

// round 16
// speedup vs baseline: 1.0778x; 1.0047x over previous
#include <cuda_runtime.h>
#include <cuda_fp16.h>
#include <math.h>
#include <stdint.h>

// Problem constants
#define B_   16384
#define F_   1024
#define H_   4096
#define O_   1024
#define E_   16
#define CAP_ 2560   // ceil(1.25 * B * 2 / 16)

// ---------------- scratch (device globals; no allocation allowed) ----------
__device__ __half  g_h[(size_t)E_ * CAP_ * H_];     // expert hidden activations (fp16)
__device__ __half  g_featr[(size_t)B_ * F_];        // features in fp16
__device__ __half  g_W1h[(size_t)E_ * F_ * H_];     // W1 in fp16
__device__ __half  g_W2h[(size_t)E_ * H_ * O_];     // W2 in fp16
__device__ int     g_inv[E_ * CAP_];
__device__ float   g_wslot[E_ * CAP_];
__device__ int     g_count[E_];
__device__ int4    g_route[B_];                     // {e0, e1, w0bits, w1bits}

// ---------------- helpers ---------------------------------------------------
__device__ __forceinline__ uint32_t smem_u32(const void* p) {
    uint32_t a;
    asm("{ .reg .u64 t; cvta.to.shared.u64 t, %1; cvt.u32.u64 %0, t; }" : "=r"(a) : "l"(p));
    return a;
}
__device__ __forceinline__ void cp_async16(uint32_t dst, const void* src) {
    asm volatile("cp.async.cg.shared.global [%0], [%1], 16;" :: "r"(dst), "l"(src));
}
__device__ __forceinline__ void cp_commit() { asm volatile("cp.async.commit_group;" ::: "memory"); }
template<int N> __device__ __forceinline__ void cp_wait() {
    asm volatile("cp.async.wait_group %0;" :: "n"(N) : "memory");
}
__device__ __forceinline__ void ldsm_x4(uint32_t r[4], uint32_t addr) {
    asm volatile("ldmatrix.sync.aligned.m8n8.x4.shared.b16 {%0,%1,%2,%3}, [%4];"
                 : "=r"(r[0]), "=r"(r[1]), "=r"(r[2]), "=r"(r[3]) : "r"(addr));
}
__device__ __forceinline__ void ldsm_x4_t(uint32_t r[4], uint32_t addr) {
    asm volatile("ldmatrix.sync.aligned.m8n8.x4.trans.shared.b16 {%0,%1,%2,%3}, [%4];"
                 : "=r"(r[0]), "=r"(r[1]), "=r"(r[2]), "=r"(r[3]) : "r"(addr));
}
__device__ __forceinline__ void mma_f16(float c[4], const uint32_t a[4],
                                        uint32_t b0, uint32_t b1) {
    asm volatile(
        "mma.sync.aligned.m16n8k16.row.col.f32.f16.f16.f32 "
        "{%0,%1,%2,%3}, {%4,%5,%6,%7}, {%8,%9}, {%0,%1,%2,%3};"
        : "+f"(c[0]), "+f"(c[1]), "+f"(c[2]), "+f"(c[3])
        : "r"(a[0]), "r"(a[1]), "r"(a[2]), "r"(a[3]), "r"(b0), "r"(b1));
}
__device__ __forceinline__ void red_add_v2(float* addr, float a, float b) {
    asm volatile("red.global.add.v2.f32 [%0], {%1, %2};"
                 :: "l"(addr), "f"(a), "f"(b) : "memory");
}

// ---------------- fused prep: gating (+feat f2h) interleaved with W1 f2h -----
#define PREP_BLOCKS 10240
#define CONV_ITERS  8                        // 8192*256*8 = 16.78M float4 = W1

__global__ __launch_bounds__(256) void prep_kernel(
    const float* __restrict__ features,
    const float* __restrict__ Wg,
    const float* __restrict__ bg,
    const float* __restrict__ ebias,
    const float* __restrict__ W1,
    __half* __restrict__ featr,
    __half* __restrict__ W1h)
{
    const int bid = blockIdx.x;
    const int q = bid / 5;
    const int r = bid - q * 5;
    if (r == 0) {
        // ---- gating + feature fp16 conversion (8 rows per block) ----
        int warp = threadIdx.x >> 5;
        int lane = threadIdx.x & 31;
        int b = q * 8 + warp;

        const float4* f4 = reinterpret_cast<const float4*>(features + (size_t)b * F_);
        __half2* h2 = reinterpret_cast<__half2*>(featr + (size_t)b * F_);
        float acc[E_];
#pragma unroll
        for (int e = 0; e < E_; e++) acc[e] = 0.f;

        for (int k4 = lane; k4 < F_ / 4; k4 += 32) {
            float4 fv = f4[k4];
            h2[2 * k4]     = __floats2half2_rn(fv.x, fv.y);
            h2[2 * k4 + 1] = __floats2half2_rn(fv.z, fv.w);
#pragma unroll
            for (int e = 0; e < E_; e++) {
                float4 wv = reinterpret_cast<const float4*>(Wg + (size_t)e * F_)[k4];
                acc[e] += fv.x * wv.x + fv.y * wv.y + fv.z * wv.z + fv.w * wv.w;
            }
        }
#pragma unroll
        for (int e = 0; e < E_; e++) {
#pragma unroll
            for (int off = 16; off > 0; off >>= 1)
                acc[e] += __shfl_xor_sync(0xFFFFFFFFu, acc[e], off);
        }
        if (lane == 0) {
            float s[E_];
#pragma unroll
            for (int e = 0; e < E_; e++) s[e] = acc[e] + bg[e] + ebias[e];
            int e0 = 0; float s0 = s[0];
#pragma unroll
            for (int e = 1; e < E_; e++) if (s[e] > s0) { s0 = s[e]; e0 = e; }
            int e1 = -1; float s1 = -3.402823e38f;
#pragma unroll
            for (int e = 0; e < E_; e++) if (e != e0 && s[e] > s1) { s1 = s[e]; e1 = e; }
            float z = expf(s1 - s0);
            float w0 = 1.f / (1.f + z);
            float w1 = z / (1.f + z);
            g_route[b] = make_int4(e0, e1, __float_as_int(w0), __float_as_int(w1));
        }
    } else {
        // ---- W1 fp32 -> fp16 conversion ----
        int c = q * 4 + (r - 1);                       // 0..8191
        size_t base = (size_t)c * (256 * CONV_ITERS) + threadIdx.x;
#pragma unroll
        for (int it = 0; it < CONV_ITERS; it++) {
            size_t j = base + (size_t)it * 256;
            float4 v = reinterpret_cast<const float4*>(W1)[j];
            reinterpret_cast<__half2*>(W1h)[2 * j]     = __floats2half2_rn(v.x, v.y);
            reinterpret_cast<__half2*>(W1h)[2 * j + 1] = __floats2half2_rn(v.z, v.w);
        }
    }
}

// ---------------- parallel capacity scan: one block per expert ---------------
// Batched: per half, prefetch 8 rounds of routing data (MLP=8), do all ballots,
// ONE barrier, then ordered prefix writes. 2 barriers / 2 exposed DRAM trips
// total (was 32 / 16).
__global__ __launch_bounds__(1024) void scan_kernel()
{
    const int e = blockIdx.x;
    const int tid = threadIdx.x;
    const int lane = tid & 31;
    const int wid = tid >> 5;
    __shared__ int warp_cnt[16][32];

    int base = 0;
#pragma unroll
    for (int half = 0; half < 2; half++) {
        int4 rt[8];
#pragma unroll
        for (int k = 0; k < 8; k++)
            rt[k] = g_route[(half * 8 + k) * 1024 + tid];

        unsigned msk[8];
#pragma unroll
        for (int k = 0; k < 8; k++) {
            bool asg = (rt[k].x == e) || (rt[k].y == e);
            msk[k] = __ballot_sync(0xFFFFFFFFu, asg);
            if (lane == 0) warp_cnt[half * 8 + k][wid] = __popc(msk[k]);
        }
        __syncthreads();

#pragma unroll
        for (int k = 0; k < 8; k++) {
            int it = half * 8 + k;
            int wbase = 0, tot = 0;
#pragma unroll
            for (int j = 0; j < 32; j++) {
                int c = warp_cnt[it][j];
                if (j < wid) wbase += c;
                tot += c;
            }
            bool asg = (rt[k].x == e) || (rt[k].y == e);
            int pos = base + wbase + __popc(msk[k] & ((1u << lane) - 1u));
            if (asg && pos < CAP_) {
                g_inv[e * CAP_ + pos] = it * 1024 + tid;
                g_wslot[e * CAP_ + pos] = (rt[k].x == e) ? __int_as_float(rt[k].z)
                                                         : __int_as_float(rt[k].w);
            }
            base += tot;
        }
    }
    if (tid == 0) g_count[e] = base < CAP_ ? base : CAP_;
}

// ---------------- fp16 tensor-core grouped GEMM ------------------------------
// CTA tile 128(m) x 128(n), BK=64, 3-stage cp.async pipeline, 128 threads,
// 2 CTAs/SM, warp tile 64x64, fragment double-buffering, peeled tail.
// VALIDATED OPTIMUM (r13/r14/r15): 2 CTAs/SM is worth ~10 pts of tensor; the
// per-SM crossbar ceiling here is ~68% tensor, measured 65.5%. Do not retune.
#define APITCH 144                                  // 128B data + 16B pad
#define BPITCH 272                                  // 256B data + 16B pad
#define STAGE_BYTES (128 * APITCH + 64 * BPITCH)    // 35840
#define NSTAGE 3
#define SMEM_TOTAL (NSTAGE * STAGE_BYTES)           // 107520 (x2 CTA = 215040)
#define MX (CAP_ / 128)                             // 20 gemm x-slices

template<int KD, int ND, bool G1>
__global__ __launch_bounds__(128, 2) void moe_gemm(
    const float* __restrict__ bias, float* __restrict__ out,
    const float* __restrict__ Wsrc, __half* __restrict__ Wdst)
{
    if (G1 && blockIdx.x >= MX) {
        // ---- W2 fp32 -> fp16 conversion slice (1024 CTAs x 16384 float4) ----
        int c = ((blockIdx.z * (int)gridDim.y + blockIdx.y) * 2 + ((int)blockIdx.x - MX));
        size_t base = (size_t)c * 16384 + threadIdx.x;
#pragma unroll
        for (int it = 0; it < 128; it++) {
            size_t j = base + (size_t)it * 128;
            float4 v = reinterpret_cast<const float4*>(Wsrc)[j];
            reinterpret_cast<__half2*>(Wdst)[2 * j]     = __floats2half2_rn(v.x, v.y);
            reinterpret_cast<__half2*>(Wdst)[2 * j + 1] = __floats2half2_rn(v.z, v.w);
        }
        return;
    }

    const int e = blockIdx.z;
    const int cnt = g_count[e];
    const int m0 = blockIdx.x * 128;
    if (m0 >= cnt) return;
    const int n0 = blockIdx.y * 128;
    constexpr int NK = KD / 64;

    extern __shared__ char smem_raw[];
    const uint32_t sbase = smem_u32(smem_raw);

    const int tid  = threadIdx.x;
    const int lane = tid & 31;
    const int wid  = tid >> 5;
    const int wm   = wid & 1;      // 2 m-warps of 64 rows
    const int wn   = wid >> 1;     // 2 n-warps of 64 cols

    // ---- loader setup ----
    const __half* pA[8];
    uint32_t dA[8];
#pragma unroll
    for (int i = 0; i < 8; i++) {
        int t = tid + 128 * i;
        int arow = t >> 3, achunk = t & 7;
        if (G1) {
            int m = m0 + arow;
            int r = (m < cnt) ? g_inv[e * CAP_ + m] : 0;
            pA[i] = g_featr + (size_t)r * KD + achunk * 8;
        } else {
            pA[i] = g_h + ((size_t)e * CAP_ + m0 + arow) * KD + achunk * 8;
        }
        dA[i] = arow * APITCH + achunk * 16;
    }
    const __half* W = G1 ? g_W1h : g_W2h;
    const __half* pB[8];
    uint32_t dB[8];
#pragma unroll
    for (int i = 0; i < 8; i++) {
        int t = tid + 128 * i;
        int brow = t >> 4, bchunk = t & 15;
        pB[i] = W + (size_t)e * KD * ND + (size_t)brow * ND + n0 + bchunk * 8;
        dB[i] = 128 * APITCH + brow * BPITCH + bchunk * 16;
    }

    auto load_stage = [&](int ko, int s) {
        uint32_t st = sbase + s * STAGE_BYTES;
#pragma unroll
        for (int i = 0; i < 8; i++)
            cp_async16(st + dA[i], pA[i] + (size_t)ko * 64);
#pragma unroll
        for (int i = 0; i < 8; i++)
            cp_async16(st + dB[i], pB[i] + (size_t)ko * 64 * ND);
        cp_commit();
    };

    load_stage(0, 0); load_stage(1, 1);

    // ---- precomputed LDSM base offsets (kk-invariant, relative to stage) ----
    const int a_lrow = (lane & 7) + ((lane >> 3) & 1) * 8;   // 0..15
    const int a_kb   = (lane >> 4);                          // 16B chunk in k16
    const int b_k    = (lane & 7) + ((lane >> 3) & 1) * 8;
    const int b_nb   = (lane >> 4) * 8;

    uint32_t aoff[4], boff[4];
#pragma unroll
    for (int im = 0; im < 4; im++)
        aoff[im] = (wm * 64 + im * 16 + a_lrow) * APITCH + a_kb * 16;
#pragma unroll
    for (int j = 0; j < 4; j++)
        boff[j] = 128 * APITCH + b_k * BPITCH + (wn * 64 + j * 16 + b_nb) * 2;

    float acc[4][8][4];
#pragma unroll
    for (int im = 0; im < 4; im++)
#pragma unroll
        for (int jn = 0; jn < 8; jn++)
#pragma unroll
            for (int q = 0; q < 4; q++) acc[im][jn][q] = 0.f;

    // fragment double buffers
    uint32_t afr[2][4][4], bfr[2][4][4];

    auto load_frags = [&](uint32_t st, int kk, int buf) {
#pragma unroll
        for (int im = 0; im < 4; im++)
            ldsm_x4(afr[buf][im], st + aoff[im] + kk * 32);
#pragma unroll
        for (int j = 0; j < 4; j++)
            ldsm_x4_t(bfr[buf][j], st + boff[j] + kk * (16 * BPITCH));
    };

    auto iter_body = [&](int s) {
        const uint32_t st = sbase + s * STAGE_BYTES;
        load_frags(st, 0, 0);
#pragma unroll
        for (int kk = 0; kk < 4; kk++) {
            if (kk < 3) load_frags(st, kk + 1, (kk + 1) & 1);
            const int cb = kk & 1;
#pragma unroll
            for (int im = 0; im < 4; im++)
#pragma unroll
                for (int jn = 0; jn < 8; jn++)
                    mma_f16(acc[im][jn], afr[cb][im],
                            bfr[cb][jn >> 1][(jn & 1) * 2],
                            bfr[cb][jn >> 1][(jn & 1) * 2 + 1]);
        }
    };

    // ---- branch-free hot loop; last two iterations peeled ----
    int s_cur = 0;          // i % 3
    int s_load = 2;         // (i+2) % 3
    for (int i = 0; i < NK - 2; i++) {
        cp_wait<1>();
        __syncthreads();
        // refill target (i+2)%3 == (i-1)%3: consumed last iter; barrier above
        // guarantees all warps are past it.
        load_stage(i + 2, s_load);
        iter_body(s_cur);
        if (++s_cur == NSTAGE) s_cur = 0;
        if (++s_load == NSTAGE) s_load = 0;
    }
    cp_wait<1>();
    __syncthreads();
    iter_body(s_cur);
    if (++s_cur == NSTAGE) s_cur = 0;

    // ---- prefetch epilogue metadata before the last mainloop iteration -----
    const int gID = lane >> 2;
    const int tig = lane & 3;
    float bb0[8], bb1[8];
#pragma unroll
    for (int jn = 0; jn < 8; jn++) {
        int c = n0 + wn * 64 + jn * 8 + tig * 2;
        bb0[jn] = bias[c];
        bb1[jn] = bias[c + 1];
    }
    int   rowi[8];
    float roww[8];
    bool  rowv[8];
    if (!G1) {
#pragma unroll
        for (int im = 0; im < 4; im++) {
            int r0 = m0 + wm * 64 + im * 16 + gID;
            int r1 = r0 + 8;
            rowv[2 * im]     = r0 < cnt;
            rowv[2 * im + 1] = r1 < cnt;
            rowi[2 * im]     = rowv[2 * im]     ? g_inv[e * CAP_ + r0] : 0;
            rowi[2 * im + 1] = rowv[2 * im + 1] ? g_inv[e * CAP_ + r1] : 0;
            roww[2 * im]     = rowv[2 * im]     ? g_wslot[e * CAP_ + r0] : 0.f;
            roww[2 * im + 1] = rowv[2 * im + 1] ? g_wslot[e * CAP_ + r1] : 0.f;
        }
    }

    cp_wait<0>();
    __syncthreads();
    iter_body(s_cur);

    // ---- epilogue ----
#pragma unroll
    for (int im = 0; im < 4; im++) {
        int r0 = m0 + wm * 64 + im * 16 + gID;
        int r1 = r0 + 8;
        if (G1) {
            bool v0 = r0 < cnt, v1 = r1 < cnt;
            __half* h0 = g_h + ((size_t)e * CAP_ + r0) * ND;
            __half* h1 = g_h + ((size_t)e * CAP_ + r1) * ND;
#pragma unroll
            for (int jn = 0; jn < 8; jn++) {
                int c = n0 + wn * 64 + jn * 8 + tig * 2;
                if (v0) {
                    __half2 h = __floats2half2_rn(fmaxf(acc[im][jn][0] + bb0[jn], 0.f),
                                                  fmaxf(acc[im][jn][1] + bb1[jn], 0.f));
                    *reinterpret_cast<__half2*>(h0 + c) = h;
                }
                if (v1) {
                    __half2 h = __floats2half2_rn(fmaxf(acc[im][jn][2] + bb0[jn], 0.f),
                                                  fmaxf(acc[im][jn][3] + bb1[jn], 0.f));
                    *reinterpret_cast<__half2*>(h1 + c) = h;
                }
            }
        } else {
            bool  v0 = rowv[2 * im],     v1 = rowv[2 * im + 1];
            int   i0 = rowi[2 * im],     i1 = rowi[2 * im + 1];
            float w0 = roww[2 * im],     w1 = roww[2 * im + 1];
#pragma unroll
            for (int jn = 0; jn < 8; jn++) {
                int c = n0 + wn * 64 + jn * 8 + tig * 2;
                if (v0) {
                    red_add_v2(out + (size_t)i0 * ND + c,
                               w0 * (acc[im][jn][0] + bb0[jn]),
                               w0 * (acc[im][jn][1] + bb1[jn]));
                }
                if (v1) {
                    red_add_v2(out + (size_t)i1 * ND + c,
                               w1 * (acc[im][jn][2] + bb0[jn]),
                               w1 * (acc[im][jn][3] + bb1[jn]));
                }
            }
        }
    }
}

// ---------------- launch ------------------------------------------------------
extern "C" void kernel_launch(void* const* d_in, const int* in_sizes, int n_in,
                              void* d_out, int out_size)
{
    const float* features = (const float*)d_in[0];
    const float* Wg       = (const float*)d_in[1];
    const float* bg       = (const float*)d_in[2];
    const float* W1       = (const float*)d_in[3];
    const float* b1       = (const float*)d_in[4];
    const float* W2       = (const float*)d_in[5];
    const float* b2       = (const float*)d_in[6];
    const float* ebias    = (const float*)d_in[7];
    float* out = (float*)d_out;

    cudaFuncSetAttribute(moe_gemm<F_, H_, true>,
                         cudaFuncAttributeMaxDynamicSharedMemorySize, SMEM_TOTAL);
    cudaFuncSetAttribute(moe_gemm<H_, O_, false>,
                         cudaFuncAttributeMaxDynamicSharedMemorySize, SMEM_TOTAL);

    cudaMemsetAsync(out, 0, (size_t)B_ * O_ * sizeof(float), 0);

    __half* d_featr; cudaGetSymbolAddress((void**)&d_featr, g_featr);
    __half* d_W1h;   cudaGetSymbolAddress((void**)&d_W1h, g_W1h);
    __half* d_W2h;   cudaGetSymbolAddress((void**)&d_W2h, g_W2h);

    prep_kernel<<<PREP_BLOCKS, 256>>>(
        features, Wg, bg, ebias, W1, d_featr, d_W1h);
    scan_kernel<<<E_, 1024>>>();

    // GEMM1 grid carries 2 extra x-slices that convert W2 (done before GEMM2).
    moe_gemm<F_, H_, true ><<<dim3(MX + 2, H_ / 128, E_), 128, SMEM_TOTAL>>>(
        b1, nullptr, W2, d_W2h);
    moe_gemm<H_, O_, false><<<dim3(MX, O_ / 128, E_), 128, SMEM_TOTAL>>>(
        b2, out, nullptr, nullptr);
}

// round 17
// speedup vs baseline: 1.0848x; 1.0065x over previous
#include <cuda_runtime.h>
#include <cuda_fp16.h>
#include <math.h>
#include <stdint.h>

// Problem constants
#define B_   16384
#define F_   1024
#define H_   4096
#define O_   1024
#define E_   16
#define CAP_ 2560   // ceil(1.25 * B * 2 / 16)

// ---------------- scratch (device globals; no allocation allowed) ----------
__device__ __half  g_h[(size_t)E_ * CAP_ * H_];     // expert hidden activations (fp16)
__device__ __half  g_featr[(size_t)B_ * F_];        // features in fp16
__device__ __half  g_W1h[(size_t)E_ * F_ * H_];     // W1 in fp16
__device__ __half  g_W2h[(size_t)E_ * H_ * O_];     // W2 in fp16
__device__ int     g_inv[E_ * CAP_];
__device__ float   g_wslot[E_ * CAP_];
__device__ int     g_count[E_];
__device__ int4    g_route[B_];                     // {e0, e1, w0bits, w1bits}

// ---------------- helpers ---------------------------------------------------
__device__ __forceinline__ uint32_t smem_u32(const void* p) {
    uint32_t a;
    asm("{ .reg .u64 t; cvta.to.shared.u64 t, %1; cvt.u32.u64 %0, t; }" : "=r"(a) : "l"(p));
    return a;
}
__device__ __forceinline__ void cp_async16(uint32_t dst, const void* src) {
    asm volatile("cp.async.cg.shared.global [%0], [%1], 16;" :: "r"(dst), "l"(src));
}
__device__ __forceinline__ void cp_commit() { asm volatile("cp.async.commit_group;" ::: "memory"); }
template<int N> __device__ __forceinline__ void cp_wait() {
    asm volatile("cp.async.wait_group %0;" :: "n"(N) : "memory");
}
__device__ __forceinline__ void ldsm_x4(uint32_t r[4], uint32_t addr) {
    asm volatile("ldmatrix.sync.aligned.m8n8.x4.shared.b16 {%0,%1,%2,%3}, [%4];"
                 : "=r"(r[0]), "=r"(r[1]), "=r"(r[2]), "=r"(r[3]) : "r"(addr));
}
__device__ __forceinline__ void ldsm_x4_t(uint32_t r[4], uint32_t addr) {
    asm volatile("ldmatrix.sync.aligned.m8n8.x4.trans.shared.b16 {%0,%1,%2,%3}, [%4];"
                 : "=r"(r[0]), "=r"(r[1]), "=r"(r[2]), "=r"(r[3]) : "r"(addr));
}
__device__ __forceinline__ void mma_f16(float c[4], const uint32_t a[4],
                                        uint32_t b0, uint32_t b1) {
    asm volatile(
        "mma.sync.aligned.m16n8k16.row.col.f32.f16.f16.f32 "
        "{%0,%1,%2,%3}, {%4,%5,%6,%7}, {%8,%9}, {%0,%1,%2,%3};"
        : "+f"(c[0]), "+f"(c[1]), "+f"(c[2]), "+f"(c[3])
        : "r"(a[0]), "r"(a[1]), "r"(a[2]), "r"(a[3]), "r"(b0), "r"(b1));
}
__device__ __forceinline__ void red_add_v2(float* addr, float a, float b) {
    asm volatile("red.global.add.v2.f32 [%0], {%1, %2};"
                 :: "l"(addr), "f"(a), "f"(b) : "memory");
}

// ---------------- fused prep: gating (+feat f2h) | W1 f2h | out zeroing ------
// Block roles interleaved by index so every scheduling wave mixes FMA-bound
// gating with DRAM-bound conversion. Zero-out blocks appended at the end
// (out must be zero before GEMM2; prep completes long before).
#define GATE_CONV_BLOCKS 10240
#define ZERO_BLOCKS 2048                     // 2048 * 2048 float4 = 64MB
#define PREP_BLOCKS (GATE_CONV_BLOCKS + ZERO_BLOCKS)
#define CONV_ITERS  8                        // 8192*256*8 = 16.78M float4 = W1

__global__ __launch_bounds__(256) void prep_kernel(
    const float* __restrict__ features,
    const float* __restrict__ Wg,
    const float* __restrict__ bg,
    const float* __restrict__ ebias,
    const float* __restrict__ W1,
    __half* __restrict__ featr,
    __half* __restrict__ W1h,
    float* __restrict__ out)
{
    const int bid = blockIdx.x;
    if (bid >= GATE_CONV_BLOCKS) {
        // ---- zero the output buffer (64MB) ----
        int z = bid - GATE_CONV_BLOCKS;
        float4* o4 = reinterpret_cast<float4*>(out) + (size_t)z * 2048 + threadIdx.x;
        const float4 zero = make_float4(0.f, 0.f, 0.f, 0.f);
#pragma unroll
        for (int it = 0; it < 8; it++)
            o4[it * 256] = zero;
        return;
    }
    const int q = bid / 5;
    const int r = bid - q * 5;
    if (r == 0) {
        // ---- gating + feature fp16 conversion (8 rows per block) ----
        int warp = threadIdx.x >> 5;
        int lane = threadIdx.x & 31;
        int b = q * 8 + warp;

        const float4* f4 = reinterpret_cast<const float4*>(features + (size_t)b * F_);
        __half2* h2 = reinterpret_cast<__half2*>(featr + (size_t)b * F_);
        float acc[E_];
#pragma unroll
        for (int e = 0; e < E_; e++) acc[e] = 0.f;

        for (int k4 = lane; k4 < F_ / 4; k4 += 32) {
            float4 fv = f4[k4];
            h2[2 * k4]     = __floats2half2_rn(fv.x, fv.y);
            h2[2 * k4 + 1] = __floats2half2_rn(fv.z, fv.w);
#pragma unroll
            for (int e = 0; e < E_; e++) {
                float4 wv = reinterpret_cast<const float4*>(Wg + (size_t)e * F_)[k4];
                acc[e] += fv.x * wv.x + fv.y * wv.y + fv.z * wv.z + fv.w * wv.w;
            }
        }
#pragma unroll
        for (int e = 0; e < E_; e++) {
#pragma unroll
            for (int off = 16; off > 0; off >>= 1)
                acc[e] += __shfl_xor_sync(0xFFFFFFFFu, acc[e], off);
        }
        if (lane == 0) {
            float s[E_];
#pragma unroll
            for (int e = 0; e < E_; e++) s[e] = acc[e] + bg[e] + ebias[e];
            int e0 = 0; float s0 = s[0];
#pragma unroll
            for (int e = 1; e < E_; e++) if (s[e] > s0) { s0 = s[e]; e0 = e; }
            int e1 = -1; float s1 = -3.402823e38f;
#pragma unroll
            for (int e = 0; e < E_; e++) if (e != e0 && s[e] > s1) { s1 = s[e]; e1 = e; }
            float z = expf(s1 - s0);
            float w0 = 1.f / (1.f + z);
            float w1 = z / (1.f + z);
            g_route[b] = make_int4(e0, e1, __float_as_int(w0), __float_as_int(w1));
        }
    } else {
        // ---- W1 fp32 -> fp16 conversion ----
        int c = q * 4 + (r - 1);                       // 0..8191
        size_t base = (size_t)c * (256 * CONV_ITERS) + threadIdx.x;
#pragma unroll
        for (int it = 0; it < CONV_ITERS; it++) {
            size_t j = base + (size_t)it * 256;
            float4 v = reinterpret_cast<const float4*>(W1)[j];
            reinterpret_cast<__half2*>(W1h)[2 * j]     = __floats2half2_rn(v.x, v.y);
            reinterpret_cast<__half2*>(W1h)[2 * j + 1] = __floats2half2_rn(v.z, v.w);
        }
    }
}

// ---------------- parallel capacity scan: one block per expert ---------------
// Batched: per half, prefetch 8 rounds of routing data (MLP=8), do all ballots,
// ONE barrier, then ordered prefix writes.
__global__ __launch_bounds__(1024) void scan_kernel()
{
    const int e = blockIdx.x;
    const int tid = threadIdx.x;
    const int lane = tid & 31;
    const int wid = tid >> 5;
    __shared__ int warp_cnt[16][32];

    int base = 0;
#pragma unroll
    for (int half = 0; half < 2; half++) {
        int4 rt[8];
#pragma unroll
        for (int k = 0; k < 8; k++)
            rt[k] = g_route[(half * 8 + k) * 1024 + tid];

        unsigned msk[8];
#pragma unroll
        for (int k = 0; k < 8; k++) {
            bool asg = (rt[k].x == e) || (rt[k].y == e);
            msk[k] = __ballot_sync(0xFFFFFFFFu, asg);
            if (lane == 0) warp_cnt[half * 8 + k][wid] = __popc(msk[k]);
        }
        __syncthreads();

#pragma unroll
        for (int k = 0; k < 8; k++) {
            int it = half * 8 + k;
            int wbase = 0, tot = 0;
#pragma unroll
            for (int j = 0; j < 32; j++) {
                int c = warp_cnt[it][j];
                if (j < wid) wbase += c;
                tot += c;
            }
            bool asg = (rt[k].x == e) || (rt[k].y == e);
            int pos = base + wbase + __popc(msk[k] & ((1u << lane) - 1u));
            if (asg && pos < CAP_) {
                g_inv[e * CAP_ + pos] = it * 1024 + tid;
                g_wslot[e * CAP_ + pos] = (rt[k].x == e) ? __int_as_float(rt[k].z)
                                                         : __int_as_float(rt[k].w);
            }
            base += tot;
        }
    }
    if (tid == 0) g_count[e] = base < CAP_ ? base : CAP_;
}

// ---------------- fp16 tensor-core grouped GEMM ------------------------------
// CTA tile 128(m) x 128(n), BK=64, 3-stage cp.async pipeline, 128 threads,
// 2 CTAs/SM, warp tile 64x64, fragment double-buffering, peeled tail.
// VALIDATED OPTIMUM (r13-r16): 2 CTAs/SM worth ~10 pts of tensor; per-SM
// crossbar ceiling ~68% tensor, measured 65.5%. Do not retune the mainloop.
#define APITCH 144                                  // 128B data + 16B pad
#define BPITCH 272                                  // 256B data + 16B pad
#define STAGE_BYTES (128 * APITCH + 64 * BPITCH)    // 35840
#define NSTAGE 3
#define SMEM_TOTAL (NSTAGE * STAGE_BYTES)           // 107520 (x2 CTA = 215040)
#define MX (CAP_ / 128)                             // 20 gemm x-slices

template<int KD, int ND, bool G1>
__global__ __launch_bounds__(128, 2) void moe_gemm(
    const float* __restrict__ bias, float* __restrict__ out,
    const float* __restrict__ Wsrc, __half* __restrict__ Wdst)
{
    if (G1 && blockIdx.x >= MX) {
        // ---- W2 fp32 -> fp16 conversion slice (1024 CTAs x 16384 float4) ----
        int c = ((blockIdx.z * (int)gridDim.y + blockIdx.y) * 2 + ((int)blockIdx.x - MX));
        size_t base = (size_t)c * 16384 + threadIdx.x;
#pragma unroll
        for (int it = 0; it < 128; it++) {
            size_t j = base + (size_t)it * 128;
            float4 v = reinterpret_cast<const float4*>(Wsrc)[j];
            reinterpret_cast<__half2*>(Wdst)[2 * j]     = __floats2half2_rn(v.x, v.y);
            reinterpret_cast<__half2*>(Wdst)[2 * j + 1] = __floats2half2_rn(v.z, v.w);
        }
        return;
    }

    const int e = blockIdx.z;
    const int cnt = g_count[e];
    const int m0 = blockIdx.x * 128;
    if (m0 >= cnt) return;
    const int n0 = blockIdx.y * 128;
    constexpr int NK = KD / 64;

    extern __shared__ char smem_raw[];
    const uint32_t sbase = smem_u32(smem_raw);

    const int tid  = threadIdx.x;
    const int lane = tid & 31;
    const int wid  = tid >> 5;
    const int wm   = wid & 1;      // 2 m-warps of 64 rows
    const int wn   = wid >> 1;     // 2 n-warps of 64 cols

    // ---- loader setup ----
    const __half* pA[8];
    uint32_t dA[8];
#pragma unroll
    for (int i = 0; i < 8; i++) {
        int t = tid + 128 * i;
        int arow = t >> 3, achunk = t & 7;
        if (G1) {
            int m = m0 + arow;
            int r = (m < cnt) ? g_inv[e * CAP_ + m] : 0;
            pA[i] = g_featr + (size_t)r * KD + achunk * 8;
        } else {
            pA[i] = g_h + ((size_t)e * CAP_ + m0 + arow) * KD + achunk * 8;
        }
        dA[i] = arow * APITCH + achunk * 16;
    }
    const __half* W = G1 ? g_W1h : g_W2h;
    const __half* pB[8];
    uint32_t dB[8];
#pragma unroll
    for (int i = 0; i < 8; i++) {
        int t = tid + 128 * i;
        int brow = t >> 4, bchunk = t & 15;
        pB[i] = W + (size_t)e * KD * ND + (size_t)brow * ND + n0 + bchunk * 8;
        dB[i] = 128 * APITCH + brow * BPITCH + bchunk * 16;
    }

    auto load_stage = [&](int ko, int s) {
        uint32_t st = sbase + s * STAGE_BYTES;
#pragma unroll
        for (int i = 0; i < 8; i++)
            cp_async16(st + dA[i], pA[i] + (size_t)ko * 64);
#pragma unroll
        for (int i = 0; i < 8; i++)
            cp_async16(st + dB[i], pB[i] + (size_t)ko * 64 * ND);
        cp_commit();
    };

    load_stage(0, 0); load_stage(1, 1);

    // ---- precomputed LDSM base offsets (kk-invariant, relative to stage) ----
    const int a_lrow = (lane & 7) + ((lane >> 3) & 1) * 8;   // 0..15
    const int a_kb   = (lane >> 4);                          // 16B chunk in k16
    const int b_k    = (lane & 7) + ((lane >> 3) & 1) * 8;
    const int b_nb   = (lane >> 4) * 8;

    uint32_t aoff[4], boff[4];
#pragma unroll
    for (int im = 0; im < 4; im++)
        aoff[im] = (wm * 64 + im * 16 + a_lrow) * APITCH + a_kb * 16;
#pragma unroll
    for (int j = 0; j < 4; j++)
        boff[j] = 128 * APITCH + b_k * BPITCH + (wn * 64 + j * 16 + b_nb) * 2;

    float acc[4][8][4];
#pragma unroll
    for (int im = 0; im < 4; im++)
#pragma unroll
        for (int jn = 0; jn < 8; jn++)
#pragma unroll
            for (int q = 0; q < 4; q++) acc[im][jn][q] = 0.f;

    // fragment double buffers
    uint32_t afr[2][4][4], bfr[2][4][4];

    auto load_frags = [&](uint32_t st, int kk, int buf) {
#pragma unroll
        for (int im = 0; im < 4; im++)
            ldsm_x4(afr[buf][im], st + aoff[im] + kk * 32);
#pragma unroll
        for (int j = 0; j < 4; j++)
            ldsm_x4_t(bfr[buf][j], st + boff[j] + kk * (16 * BPITCH));
    };

    auto iter_body = [&](int s) {
        const uint32_t st = sbase + s * STAGE_BYTES;
        load_frags(st, 0, 0);
#pragma unroll
        for (int kk = 0; kk < 4; kk++) {
            if (kk < 3) load_frags(st, kk + 1, (kk + 1) & 1);
            const int cb = kk & 1;
#pragma unroll
            for (int im = 0; im < 4; im++)
#pragma unroll
                for (int jn = 0; jn < 8; jn++)
                    mma_f16(acc[im][jn], afr[cb][im],
                            bfr[cb][jn >> 1][(jn & 1) * 2],
                            bfr[cb][jn >> 1][(jn & 1) * 2 + 1]);
        }
    };

    // ---- branch-free hot loop; last two iterations peeled ----
    int s_cur = 0;          // i % 3
    int s_load = 2;         // (i+2) % 3
    for (int i = 0; i < NK - 2; i++) {
        cp_wait<1>();
        __syncthreads();
        // refill target (i+2)%3 == (i-1)%3: consumed last iter; barrier above
        // guarantees all warps are past it.
        load_stage(i + 2, s_load);
        iter_body(s_cur);
        if (++s_cur == NSTAGE) s_cur = 0;
        if (++s_load == NSTAGE) s_load = 0;
    }
    cp_wait<1>();
    __syncthreads();
    iter_body(s_cur);
    if (++s_cur == NSTAGE) s_cur = 0;

    // ---- prefetch epilogue metadata before the last mainloop iteration -----
    const int gID = lane >> 2;
    const int tig = lane & 3;
    float bb0[8], bb1[8];
#pragma unroll
    for (int jn = 0; jn < 8; jn++) {
        int c = n0 + wn * 64 + jn * 8 + tig * 2;
        bb0[jn] = bias[c];
        bb1[jn] = bias[c + 1];
    }
    int   rowi[8];
    float roww[8];
    bool  rowv[8];
    if (!G1) {
#pragma unroll
        for (int im = 0; im < 4; im++) {
            int r0 = m0 + wm * 64 + im * 16 + gID;
            int r1 = r0 + 8;
            rowv[2 * im]     = r0 < cnt;
            rowv[2 * im + 1] = r1 < cnt;
            rowi[2 * im]     = rowv[2 * im]     ? g_inv[e * CAP_ + r0] : 0;
            rowi[2 * im + 1] = rowv[2 * im + 1] ? g_inv[e * CAP_ + r1] : 0;
            roww[2 * im]     = rowv[2 * im]     ? g_wslot[e * CAP_ + r0] : 0.f;
            roww[2 * im + 1] = rowv[2 * im + 1] ? g_wslot[e * CAP_ + r1] : 0.f;
        }
    }

    cp_wait<0>();
    __syncthreads();
    iter_body(s_cur);

    // ---- epilogue ----
#pragma unroll
    for (int im = 0; im < 4; im++) {
        int r0 = m0 + wm * 64 + im * 16 + gID;
        int r1 = r0 + 8;
        if (G1) {
            bool v0 = r0 < cnt, v1 = r1 < cnt;
            __half* h0 = g_h + ((size_t)e * CAP_ + r0) * ND;
            __half* h1 = g_h + ((size_t)e * CAP_ + r1) * ND;
#pragma unroll
            for (int jn = 0; jn < 8; jn++) {
                int c = n0 + wn * 64 + jn * 8 + tig * 2;
                if (v0) {
                    __half2 h = __floats2half2_rn(fmaxf(acc[im][jn][0] + bb0[jn], 0.f),
                                                  fmaxf(acc[im][jn][1] + bb1[jn], 0.f));
                    *reinterpret_cast<__half2*>(h0 + c) = h;
                }
                if (v1) {
                    __half2 h = __floats2half2_rn(fmaxf(acc[im][jn][2] + bb0[jn], 0.f),
                                                  fmaxf(acc[im][jn][3] + bb1[jn], 0.f));
                    *reinterpret_cast<__half2*>(h1 + c) = h;
                }
            }
        } else {
            bool  v0 = rowv[2 * im],     v1 = rowv[2 * im + 1];
            int   i0 = rowi[2 * im],     i1 = rowi[2 * im + 1];
            float w0 = roww[2 * im],     w1 = roww[2 * im + 1];
#pragma unroll
            for (int jn = 0; jn < 8; jn++) {
                int c = n0 + wn * 64 + jn * 8 + tig * 2;
                if (v0) {
                    red_add_v2(out + (size_t)i0 * ND + c,
                               w0 * (acc[im][jn][0] + bb0[jn]),
                               w0 * (acc[im][jn][1] + bb1[jn]));
                }
                if (v1) {
                    red_add_v2(out + (size_t)i1 * ND + c,
                               w1 * (acc[im][jn][2] + bb0[jn]),
                               w1 * (acc[im][jn][3] + bb1[jn]));
                }
            }
        }
    }
}

// ---------------- launch ------------------------------------------------------
extern "C" void kernel_launch(void* const* d_in, const int* in_sizes, int n_in,
                              void* d_out, int out_size)
{
    const float* features = (const float*)d_in[0];
    const float* Wg       = (const float*)d_in[1];
    const float* bg       = (const float*)d_in[2];
    const float* W1       = (const float*)d_in[3];
    const float* b1       = (const float*)d_in[4];
    const float* W2       = (const float*)d_in[5];
    const float* b2       = (const float*)d_in[6];
    const float* ebias    = (const float*)d_in[7];
    float* out = (float*)d_out;

    cudaFuncSetAttribute(moe_gemm<F_, H_, true>,
                         cudaFuncAttributeMaxDynamicSharedMemorySize, SMEM_TOTAL);
    cudaFuncSetAttribute(moe_gemm<H_, O_, false>,
                         cudaFuncAttributeMaxDynamicSharedMemorySize, SMEM_TOTAL);

    __half* d_featr; cudaGetSymbolAddress((void**)&d_featr, g_featr);
    __half* d_W1h;   cudaGetSymbolAddress((void**)&d_W1h, g_W1h);
    __half* d_W2h;   cudaGetSymbolAddress((void**)&d_W2h, g_W2h);

    // prep also zeroes `out` (zero blocks appended); no separate memset node.
    prep_kernel<<<PREP_BLOCKS, 256>>>(
        features, Wg, bg, ebias, W1, d_featr, d_W1h, out);
    scan_kernel<<<E_, 1024>>>();

    // GEMM1 grid carries 2 extra x-slices that convert W2 (done before GEMM2).
    moe_gemm<F_, H_, true ><<<dim3(MX + 2, H_ / 128, E_), 128, SMEM_TOTAL>>>(
        b1, nullptr, W2, d_W2h);
    moe_gemm<H_, O_, false><<<dim3(MX, O_ / 128, E_), 128, SMEM_TOTAL>>>(
        b2, out, nullptr, nullptr);
}